// round 2
// baseline (speedup 1.0000x reference)
#include <cuda_runtime.h>
#include <cuda_bf16.h>
#include <cstdint>

// Problem constants
#define BATCH 2
#define SEQ   2048
#define EMB   1024
#define HEADS 16
#define HDIM  64
#define MTOK  (BATCH * SEQ)        // 4096 tokens

// ---------------------------------------------------------------------------
// Scratch (allocation-free: device globals)
// ---------------------------------------------------------------------------
__device__ float g_qkv[(size_t)MTOK * 3 * EMB];   // [M, 3E]
__device__ float g_attn[(size_t)MTOK * EMB];      // [M, E]

// ---------------------------------------------------------------------------
// Tiled SGEMM: C[M,N] = A[M,K] @ W[K,N] + bias[N]
// BM=BN=128, BK=16, 256 threads, 8x8 per thread (split 4+4 mapping)
// ---------------------------------------------------------------------------
#define BM 128
#define BN 128
#define BKK 16

__global__ __launch_bounds__(256) void gemm_bias_kernel(
    const float* __restrict__ A, const float* __restrict__ W,
    const float* __restrict__ bias, float* __restrict__ C,
    int M, int N, int K)
{
    __shared__ float As[BKK][BM];
    __shared__ float Ws[BKK][BN];

    const int tid = threadIdx.x;
    const int tx = tid & 15;          // 0..15  (cols)
    const int ty = tid >> 4;          // 0..15  (rows)
    const int row0 = blockIdx.y * BM;
    const int col0 = blockIdx.x * BN;

    float acc[8][8];
#pragma unroll
    for (int i = 0; i < 8; i++)
#pragma unroll
        for (int j = 0; j < 8; j++) acc[i][j] = 0.f;

    for (int kt = 0; kt < K; kt += BKK) {
        // load A tile (128x16) and W tile (16x128): 512 float4 each, 2 per thread
#pragma unroll
        for (int it = 0; it < 2; it++) {
            int i = tid + it * 256;
            int r  = i >> 2;
            int c4 = (i & 3) * 4;
            float4 a = *(const float4*)(A + (size_t)(row0 + r) * K + kt + c4);
            As[c4 + 0][r] = a.x;
            As[c4 + 1][r] = a.y;
            As[c4 + 2][r] = a.z;
            As[c4 + 3][r] = a.w;
            int wr = i >> 5;
            int wc = (i & 31) * 4;
            float4 w = *(const float4*)(W + (size_t)(kt + wr) * N + col0 + wc);
            *(float4*)(&Ws[wr][wc]) = w;
        }
        __syncthreads();

#pragma unroll
        for (int k = 0; k < BKK; k++) {
            float ra[8], rb[8];
            float4 a0 = *(const float4*)(&As[k][ty * 4]);
            float4 a1 = *(const float4*)(&As[k][64 + ty * 4]);
            ra[0]=a0.x; ra[1]=a0.y; ra[2]=a0.z; ra[3]=a0.w;
            ra[4]=a1.x; ra[5]=a1.y; ra[6]=a1.z; ra[7]=a1.w;
            float4 b0 = *(const float4*)(&Ws[k][tx * 4]);
            float4 b1 = *(const float4*)(&Ws[k][64 + tx * 4]);
            rb[0]=b0.x; rb[1]=b0.y; rb[2]=b0.z; rb[3]=b0.w;
            rb[4]=b1.x; rb[5]=b1.y; rb[6]=b1.z; rb[7]=b1.w;
#pragma unroll
            for (int i = 0; i < 8; i++)
#pragma unroll
                for (int j = 0; j < 8; j++)
                    acc[i][j] += ra[i] * rb[j];
        }
        __syncthreads();
    }

    // epilogue
#pragma unroll
    for (int ib = 0; ib < 2; ib++) {
#pragma unroll
        for (int i = 0; i < 4; i++) {
            int r = row0 + ib * 64 + ty * 4 + i;
#pragma unroll
            for (int jb = 0; jb < 2; jb++) {
                int c = col0 + jb * 64 + tx * 4;
                float4 o;
                o.x = acc[ib * 4 + i][jb * 4 + 0] + bias[c + 0];
                o.y = acc[ib * 4 + i][jb * 4 + 1] + bias[c + 1];
                o.z = acc[ib * 4 + i][jb * 4 + 2] + bias[c + 2];
                o.w = acc[ib * 4 + i][jb * 4 + 3] + bias[c + 3];
                *(float4*)(C + (size_t)r * N + c) = o;
            }
        }
    }
}

// ---------------------------------------------------------------------------
// Flash attention, fp32.  One block per (q-tile of 64, head, batch).
// 256 threads = 16x16, each thread owns a 4x4 of the 64x64 score tile and a
// 4x4 of the 64x64 output tile.
//
// Smem layout (all [64][64], 16KB each, 64KB total):
//   Qt, Kt : TRANSPOSED (depth-major), float4-group swizzled by (row & 15)
//   Pt     : probabilities TRANSPOSED (kv-major), same swizzle
//   Vs     : plain row-major [kv][d]
// All inner-loop reads are aligned LDS.128, conflict-free or broadcast.
// ---------------------------------------------------------------------------
#define BQ  64
#define BKV 64
#define FLASH_SMEM (4 * 64 * 64 * 4)   // 65536 bytes

// swizzled float index inside a 64-float row: row-major (row, col)
__device__ __forceinline__ int swz(int row, int col) {
    return row * 64 + ((((col >> 2) ^ (row & 15)) << 2) | (col & 3));
}

__global__ __launch_bounds__(256) void flash_kernel(
    const float* __restrict__ qkv, float* __restrict__ out)
{
    extern __shared__ float smem[];
    float* Qt = smem;                 // [d][qrow]  swizzled
    float* Kt = smem + 64 * 64;       // [d][krow]  swizzled
    float* Vs = smem + 2 * 64 * 64;   // [krow][d]  plain
    float* Pt = smem + 3 * 64 * 64;   // [krow][qrow] swizzled

    const int tid = threadIdx.x;
    const int tx = tid & 15;
    const int ty = tid >> 4;
    const int q0 = blockIdx.x * BQ;
    const int h  = blockIdx.y;
    const int b  = blockIdx.z;

    const size_t rowstride = 3 * EMB;
    const float* qbase = qkv + (size_t)b * SEQ * rowstride + h * HDIM;
    const float* kbase = qbase + EMB;
    const float* vbase = qbase + 2 * EMB;
    const float sm_scale = 0.125f;   // 1/sqrt(64)

    // load Q tile (64 rows x 64 d), transposed + swizzled, pre-scaled
#pragma unroll
    for (int it = 0; it < 4; it++) {
        int i = tid + it * 256;              // float4 slot 0..1023
        int r = i >> 4;                      // q row 0..63
        int c = (i & 15) * 4;                // d col 0..60
        float4 v = *(const float4*)(qbase + (size_t)(q0 + r) * rowstride + c);
        Qt[swz(c + 0, r)] = v.x * sm_scale;
        Qt[swz(c + 1, r)] = v.y * sm_scale;
        Qt[swz(c + 2, r)] = v.z * sm_scale;
        Qt[swz(c + 3, r)] = v.w * sm_scale;
    }

    float m[4], l[4], O[4][4];
#pragma unroll
    for (int i = 0; i < 4; i++) {
        m[i] = -1e30f;
        l[i] = 0.f;
#pragma unroll
        for (int j = 0; j < 4; j++) O[i][j] = 0.f;
    }

    for (int j0 = 0; j0 < SEQ; j0 += BKV) {
        __syncthreads();   // previous iteration's Kt/Vs reads complete
        // load K (transposed+swizzled) and V (plain) tiles
#pragma unroll
        for (int it = 0; it < 4; it++) {
            int i = tid + it * 256;
            int r = i >> 4;
            int c = (i & 15) * 4;
            float4 kv = *(const float4*)(kbase + (size_t)(j0 + r) * rowstride + c);
            Kt[swz(c + 0, r)] = kv.x;
            Kt[swz(c + 1, r)] = kv.y;
            Kt[swz(c + 2, r)] = kv.z;
            Kt[swz(c + 3, r)] = kv.w;
            float4 vv = *(const float4*)(vbase + (size_t)(j0 + r) * rowstride + c);
            *(float4*)(Vs + r * 64 + c) = vv;
        }
        __syncthreads();

        // S = Q @ K^T : per d, one broadcast LDS.128 (q) + one cf LDS.128 (k)
        float s[4][4];
#pragma unroll
        for (int i = 0; i < 4; i++)
#pragma unroll
            for (int j = 0; j < 4; j++) s[i][j] = 0.f;

#pragma unroll 8
        for (int d = 0; d < HDIM; d++) {
            float4 q4 = *(const float4*)(Qt + d * 64 + (((ty ^ (d & 15)) << 2)));
            float4 k4 = *(const float4*)(Kt + d * 64 + (((tx ^ (d & 15)) << 2)));
            float qv[4] = {q4.x, q4.y, q4.z, q4.w};
            float kv[4] = {k4.x, k4.y, k4.z, k4.w};
#pragma unroll
            for (int i = 0; i < 4; i++)
#pragma unroll
                for (int j = 0; j < 4; j++)
                    s[i][j] += qv[i] * kv[j];
        }

        // online softmax per q-row (rows ty*4+i shared by 16 lanes of same ty)
#pragma unroll
        for (int i = 0; i < 4; i++) {
            float mx = s[i][0];
#pragma unroll
            for (int j = 1; j < 4; j++) mx = fmaxf(mx, s[i][j]);
#pragma unroll
            for (int o = 8; o >= 1; o >>= 1)
                mx = fmaxf(mx, __shfl_xor_sync(0xffffffffu, mx, o));
            float mnew  = fmaxf(m[i], mx);
            float alpha = __expf(m[i] - mnew);
            m[i] = mnew;
            float rsum = 0.f;
#pragma unroll
            for (int j = 0; j < 4; j++) {
                s[i][j] = __expf(s[i][j] - mnew);
                rsum += s[i][j];
            }
#pragma unroll
            for (int o = 8; o >= 1; o >>= 1)
                rsum += __shfl_xor_sync(0xffffffffu, rsum, o);
            l[i] = l[i] * alpha + rsum;
#pragma unroll
            for (int j = 0; j < 4; j++) O[i][j] *= alpha;
        }

        // store P transposed: Pt[kcol][qrow], float4 over qrow (i) per kcol (j)
#pragma unroll
        for (int j = 0; j < 4; j++) {
            int krow = tx * 4 + j;
            float4 pv = make_float4(s[0][j], s[1][j], s[2][j], s[3][j]);
            *(float4*)(Pt + krow * 64 + (((ty ^ (krow & 15)) << 2))) = pv;
        }
        __syncthreads();   // all of Pt written

        // O += P @ V : per kv row, one broadcast LDS.128 (p) + one cf LDS.128 (v)
#pragma unroll 8
        for (int k = 0; k < BKV; k++) {
            float4 p4 = *(const float4*)(Pt + k * 64 + (((ty ^ (k & 15)) << 2)));
            float4 v4 = *(const float4*)(Vs + k * 64 + (tx << 2));
            float pv[4] = {p4.x, p4.y, p4.z, p4.w};
            float vv[4] = {v4.x, v4.y, v4.z, v4.w};
#pragma unroll
            for (int i = 0; i < 4; i++)
#pragma unroll
                for (int j = 0; j < 4; j++)
                    O[i][j] += pv[i] * vv[j];
        }
    }

    // epilogue: normalize and write [B,S,E]
#pragma unroll
    for (int i = 0; i < 4; i++) {
        float inv = 1.f / l[i];
        int r = q0 + ty * 4 + i;
        float* dst = out + ((size_t)b * SEQ + r) * EMB + h * HDIM + tx * 4;
        float4 o = make_float4(O[i][0] * inv, O[i][1] * inv,
                               O[i][2] * inv, O[i][3] * inv);
        *(float4*)dst = o;
    }
}

// ---------------------------------------------------------------------------
// Launch
// ---------------------------------------------------------------------------
extern "C" void kernel_launch(void* const* d_in, const int* in_sizes, int n_in,
                              void* d_out, int out_size)
{
    // identify inputs by element count (robust to ordering)
    const float *x = nullptr, *Wqkv = nullptr, *bqkv = nullptr,
                *Wout = nullptr, *bout = nullptr;
    for (int i = 0; i < n_in; i++) {
        switch (in_sizes[i]) {
            case 4194304: x    = (const float*)d_in[i]; break;  // [2,2048,1024]
            case 3145728: Wqkv = (const float*)d_in[i]; break;  // [1024,3072]
            case 3072:    bqkv = (const float*)d_in[i]; break;
            case 1048576: Wout = (const float*)d_in[i]; break;  // [1024,1024]
            case 1024:    bout = (const float*)d_in[i]; break;
        }
    }
    float* out = (float*)d_out;

    float* qkv;  cudaGetSymbolAddress((void**)&qkv,  g_qkv);
    float* attn; cudaGetSymbolAddress((void**)&attn, g_attn);

    static bool attr_set = false;
    if (!attr_set) {
        cudaFuncSetAttribute(flash_kernel,
                             cudaFuncAttributeMaxDynamicSharedMemorySize,
                             FLASH_SMEM);
        attr_set = true;
    }

    // 1. QKV projection: [4096,1024] @ [1024,3072] + bias
    {
        dim3 grid(3 * EMB / BN, MTOK / BM);
        gemm_bias_kernel<<<grid, 256>>>(x, Wqkv, bqkv, qkv, MTOK, 3 * EMB, EMB);
    }
    // 2. Flash attention over heads
    {
        dim3 grid(SEQ / BQ, HEADS, BATCH);
        flash_kernel<<<grid, 256, FLASH_SMEM>>>(qkv, attn);
    }
    // 3. Output projection: [4096,1024] @ [1024,1024] + bias
    {
        dim3 grid(EMB / BN, MTOK / BM);
        gemm_bias_kernel<<<grid, 256>>>(attn, Wout, bout, out, MTOK, EMB, EMB);
    }
}

// round 4
// speedup vs baseline: 2.9095x; 2.9095x over previous
#include <cuda_runtime.h>
#include <cuda_bf16.h>
#include <cstdint>

// Problem constants
#define BATCH 2
#define SEQ   2048
#define EMB   1024
#define HEADS 16
#define HDIM  64
#define MTOK  (BATCH * SEQ)        // 4096 tokens

// ---------------------------------------------------------------------------
// Scratch (allocation-free: device globals), all bf16 hi/lo pairs
// ---------------------------------------------------------------------------
__device__ __nv_bfloat16 g_xh[(size_t)MTOK * EMB],  g_xl[(size_t)MTOK * EMB];
__device__ __nv_bfloat16 g_qkvh[(size_t)MTOK * 3 * EMB], g_qkvl[(size_t)MTOK * 3 * EMB];
__device__ __nv_bfloat16 g_ah[(size_t)MTOK * EMB],  g_al[(size_t)MTOK * EMB];
__device__ __nv_bfloat16 g_wqh[(size_t)3 * EMB * EMB], g_wql[(size_t)3 * EMB * EMB]; // W_qkv^T [3E,E]
__device__ __nv_bfloat16 g_woh[(size_t)EMB * EMB],     g_wol[(size_t)EMB * EMB];     // W_out^T [E,E]

// ---------------------------------------------------------------------------
// Helpers: cp.async, ldmatrix, mma.sync (all portable compute_100 PTX)
// ---------------------------------------------------------------------------
__device__ __forceinline__ uint32_t smem_u32(const void* p) {
    uint32_t a;
    asm("{ .reg .u64 t; cvta.to.shared.u64 t, %1; cvt.u32.u64 %0, t; }"
        : "=r"(a) : "l"(p));
    return a;
}
#define CP_ASYNC16(dst, src) \
    asm volatile("cp.async.cg.shared.global [%0], [%1], 16;" :: "r"(dst), "l"(src))
#define CP_COMMIT() asm volatile("cp.async.commit_group;" ::: "memory")
#define CP_WAIT0()  asm volatile("cp.async.wait_group 0;" ::: "memory")
#define CP_WAIT1()  asm volatile("cp.async.wait_group 1;" ::: "memory")

__device__ __forceinline__ void ldsm4(uint32_t a[4], uint32_t addr) {
    asm volatile("ldmatrix.sync.aligned.m8n8.x4.shared.b16 {%0,%1,%2,%3}, [%4];"
        : "=r"(a[0]), "=r"(a[1]), "=r"(a[2]), "=r"(a[3]) : "r"(addr));
}
__device__ __forceinline__ void ldsm4t(uint32_t a[4], uint32_t addr) {
    asm volatile("ldmatrix.sync.aligned.m8n8.x4.trans.shared.b16 {%0,%1,%2,%3}, [%4];"
        : "=r"(a[0]), "=r"(a[1]), "=r"(a[2]), "=r"(a[3]) : "r"(addr));
}
__device__ __forceinline__ void mma16816(float c[4], const uint32_t a[4],
                                         uint32_t b0, uint32_t b1) {
    asm volatile("mma.sync.aligned.m16n8k16.row.col.f32.bf16.bf16.f32 "
                 "{%0,%1,%2,%3}, {%4,%5,%6,%7}, {%8,%9}, {%0,%1,%2,%3};"
                 : "+f"(c[0]), "+f"(c[1]), "+f"(c[2]), "+f"(c[3])
                 : "r"(a[0]), "r"(a[1]), "r"(a[2]), "r"(a[3]), "r"(b0), "r"(b1));
}

__device__ __forceinline__ void packsplit(float x, float y,
                                          uint32_t& hi, uint32_t& lo) {
    __nv_bfloat16 hx = __float2bfloat16_rn(x);
    __nv_bfloat16 hy = __float2bfloat16_rn(y);
    __nv_bfloat162 h2(hx, hy);
    hi = *reinterpret_cast<uint32_t*>(&h2);
    __nv_bfloat16 lx = __float2bfloat16_rn(x - __bfloat162float(hx));
    __nv_bfloat16 ly = __float2bfloat16_rn(y - __bfloat162float(hy));
    __nv_bfloat162 l2(lx, ly);
    lo = *reinterpret_cast<uint32_t*>(&l2);
}

// ---------------------------------------------------------------------------
// Conversion kernels
// ---------------------------------------------------------------------------
__global__ __launch_bounds__(256) void split_kernel(
    const float* __restrict__ in, __nv_bfloat16* __restrict__ hi,
    __nv_bfloat16* __restrict__ lo, int n4)
{
    int i = blockIdx.x * blockDim.x + threadIdx.x;
    if (i >= n4) return;
    float4 v = ((const float4*)in)[i];
    uint32_t h0, l0, h1, l1;
    packsplit(v.x, v.y, h0, l0);
    packsplit(v.z, v.w, h1, l1);
    ((uint32_t*)hi)[i * 2]     = h0;
    ((uint32_t*)hi)[i * 2 + 1] = h1;
    ((uint32_t*)lo)[i * 2]     = l0;
    ((uint32_t*)lo)[i * 2 + 1] = l1;
}

// W[K,N] -> T_hi/T_lo [N,K]
__global__ __launch_bounds__(256) void transpose_split_kernel(
    const float* __restrict__ W, __nv_bfloat16* __restrict__ Th,
    __nv_bfloat16* __restrict__ Tl, int K, int N)
{
    __shared__ float t[32][33];
    int n0 = blockIdx.x * 32, k0 = blockIdx.y * 32;
#pragma unroll
    for (int r = threadIdx.y; r < 32; r += 8)
        t[r][threadIdx.x] = W[(size_t)(k0 + r) * N + n0 + threadIdx.x];
    __syncthreads();
#pragma unroll
    for (int r = threadIdx.y; r < 32; r += 8) {
        float v = t[threadIdx.x][r];          // W[k0+tx][n0+r]
        __nv_bfloat16 h = __float2bfloat16_rn(v);
        __nv_bfloat16 l = __float2bfloat16_rn(v - __bfloat162float(h));
        size_t o = (size_t)(n0 + r) * K + k0 + threadIdx.x;
        Th[o] = h;
        Tl[o] = l;
    }
}

// ---------------------------------------------------------------------------
// Split-bf16 GEMM via mma.sync: C[M,N] = (Ah+Al)[M,K] @ (Bh+Bl)[N,K]^T + bias
// Virtual K-extension: phases (Ah,Bh), (Al,Bh), (Ah,Bl) accumulate the 3-term
// split product in one plain pipeline. Tile 128x128, BK=64, 2-stage cp.async.
// 8 warps: warp (wm = wid>>1 in 0..3, wn = wid&1) owns 32m x 64n.
// Output: fp32 (Cf != nullptr) or bf16 hi/lo pair (Ch/Cl).
// ---------------------------------------------------------------------------
#define GEMM_SMEM (2 * 32768)

__global__ __launch_bounds__(256) void gemm_mma_kernel(
    const __nv_bfloat16* __restrict__ Ah, const __nv_bfloat16* __restrict__ Al,
    const __nv_bfloat16* __restrict__ Bh, const __nv_bfloat16* __restrict__ Bl,
    const float* __restrict__ bias,
    float* __restrict__ Cf,
    __nv_bfloat16* __restrict__ Ch, __nv_bfloat16* __restrict__ Cl,
    int M, int N, int K)
{
    extern __shared__ char smem[];
    uint32_t sbase = smem_u32(smem);

    const int tid  = threadIdx.x;
    const int lane = tid & 31;
    const int wid  = tid >> 5;
    const int wm   = wid >> 1;
    const int wn   = wid & 1;
    const int row0 = blockIdx.y * 128;
    const int col0 = blockIdx.x * 128;
    const int KC   = K >> 6;           // 64-wide chunks per phase
    const int NST  = 3 * KC;
    const int grp  = lane >> 3, l8 = lane & 7;

    float c[2][8][4];
#pragma unroll
    for (int mb = 0; mb < 2; mb++)
#pragma unroll
        for (int nb = 0; nb < 8; nb++)
#pragma unroll
            for (int q = 0; q < 4; q++) c[mb][nb][q] = 0.f;

    auto load_stage = [&](int s, int buf) {
        int ph = s >= 2 * KC ? 2 : (s >= KC ? 1 : 0);
        int k0 = (s - ph * KC) << 6;
        const __nv_bfloat16* ap = (ph == 1) ? Al : Ah;
        const __nv_bfloat16* bp = (ph == 2) ? Bl : Bh;
        const char* ab = (const char*)(ap + (size_t)row0 * K + k0);
        const char* bb = (const char*)(bp + (size_t)col0 * K + k0);
        uint32_t dstb = sbase + (uint32_t)buf * 32768u;
#pragma unroll
        for (int it = 0; it < 8; it++) {
            int cch = tid + it * 256;       // 0..2047
            int arr = cch >> 10;            // 0 = A, 1 = B
            int cc  = cch & 1023;
            int r   = cc >> 3, ch = cc & 7;
            const char* src = (arr ? bb : ab) + (size_t)r * (K * 2) + ch * 16;
            uint32_t dst = dstb + (uint32_t)arr * 16384u
                         + (uint32_t)(r * 128 + ((ch ^ (r & 7)) << 4));
            CP_ASYNC16(dst, src);
        }
    };

    load_stage(0, 0);
    CP_COMMIT();

    for (int s = 0; s < NST; s++) {
        int buf = s & 1;
        if (s + 1 < NST) {
            load_stage(s + 1, buf ^ 1);
            CP_COMMIT();
            CP_WAIT1();
        } else {
            CP_WAIT0();
        }
        __syncthreads();

        uint32_t abase = sbase + (uint32_t)buf * 32768u;
        uint32_t bbase = abase + 16384u;
#pragma unroll
        for (int kc = 0; kc < 4; kc++) {
            uint32_t afr[2][4];
#pragma unroll
            for (int mb = 0; mb < 2; mb++) {
                int row = wm * 32 + mb * 16 + (grp & 1) * 8 + l8;
                int ch  = 2 * kc + (grp >> 1);
                ldsm4(afr[mb], abase + row * 128 + ((ch ^ (row & 7)) << 4));
            }
#pragma unroll
            for (int ng = 0; ng < 4; ng++) {
                uint32_t bfr[4];
                int row = wn * 64 + ng * 16 + (grp >> 1) * 8 + l8;
                int ch  = 2 * kc + (grp & 1);
                ldsm4(bfr, bbase + row * 128 + ((ch ^ (row & 7)) << 4));
#pragma unroll
                for (int mb = 0; mb < 2; mb++) {
                    mma16816(c[mb][2 * ng],     afr[mb], bfr[0], bfr[1]);
                    mma16816(c[mb][2 * ng + 1], afr[mb], bfr[2], bfr[3]);
                }
            }
        }
        __syncthreads();
    }

    // epilogue
#pragma unroll
    for (int mb = 0; mb < 2; mb++) {
#pragma unroll
        for (int half = 0; half < 2; half++) {
            int row = row0 + wm * 32 + mb * 16 + (lane >> 2) + half * 8;
#pragma unroll
            for (int nb = 0; nb < 8; nb++) {
                int col = col0 + wn * 64 + nb * 8 + (lane & 3) * 2;
                float v0 = c[mb][nb][2 * half]     + bias[col];
                float v1 = c[mb][nb][2 * half + 1] + bias[col + 1];
                size_t off = (size_t)row * N + col;
                if (Cf) {
                    float2 o = make_float2(v0, v1);
                    *(float2*)(Cf + off) = o;
                } else {
                    uint32_t hi, lo;
                    packsplit(v0, v1, hi, lo);
                    *(uint32_t*)(Ch + off) = hi;
                    *(uint32_t*)(Cl + off) = lo;
                }
            }
        }
    }
}

// ---------------------------------------------------------------------------
// Flash attention via mma.sync, split-bf16 QK and PV.
// CTA: 256 thr (8 warps), BQ=128 (warp w owns q-rows 16w..16w+15), BKV=64.
// smem: Qh,Ql (16KB ea), Kh,Kl,Vh,Vl (8KB ea) = 64KB; rows 128B, chunk^row
// swizzle, ldmatrix conflict-free.
// Writes output directly as bf16 hi/lo pair for GEMM2.
// ---------------------------------------------------------------------------
#define FLASH_SMEM 65536

__global__ __launch_bounds__(256) void flash_mma_kernel(
    const __nv_bfloat16* __restrict__ QKVh, const __nv_bfloat16* __restrict__ QKVl,
    __nv_bfloat16* __restrict__ Oh, __nv_bfloat16* __restrict__ Ol)
{
    extern __shared__ char smem[];
    uint32_t sb  = smem_u32(smem);
    uint32_t sQh = sb,           sQl = sb + 16384;
    uint32_t sKh = sb + 32768;   // Kl = +8192, Vh = +16384, Vl = +24576 from sKh

    const int tid  = threadIdx.x;
    const int lane = tid & 31;
    const int wid  = tid >> 5;
    const int grp  = lane >> 3, l8 = lane & 7;
    const int q0   = blockIdx.x * 128;
    const int h    = blockIdx.y;
    const int b    = blockIdx.z;

    const size_t qoff = ((size_t)b * SEQ + q0) * (3 * EMB) + h * HDIM;
    const size_t koff = ((size_t)b * SEQ) * (3 * EMB) + h * HDIM + EMB;
    const size_t voff = koff + EMB;

    // load Q tiles (hi+lo): 2 x 128 rows x 8 chunks = 2048 chunks
#pragma unroll
    for (int it = 0; it < 8; it++) {
        int cch = tid + it * 256;
        int arr = cch >> 10;
        int cc  = cch & 1023;
        int r   = cc >> 3, ch = cc & 7;
        const char* src = (const char*)((arr ? QKVl : QKVh) + qoff
                                        + (size_t)r * (3 * EMB) + ch * 8);
        uint32_t dst = (arr ? sQl : sQh)
                     + (uint32_t)(r * 128 + ((ch ^ (r & 7)) << 4));
        CP_ASYNC16(dst, src);
    }

    float m0 = -1e30f, m1 = -1e30f, l0 = 0.f, l1 = 0.f;
    float o[8][4];
#pragma unroll
    for (int d = 0; d < 8; d++)
#pragma unroll
        for (int q = 0; q < 4; q++) o[d][q] = 0.f;

    for (int j0 = 0; j0 < SEQ; j0 += 64) {
        // load K,V tiles (hi+lo): 4 arrays x 64 rows x 8 chunks
#pragma unroll
        for (int it = 0; it < 8; it++) {
            int cch = tid + it * 256;
            int arr = cch >> 9;              // 0 Kh, 1 Kl, 2 Vh, 3 Vl
            int cc  = cch & 511;
            int r   = cc >> 3, ch = cc & 7;
            size_t goff = ((arr < 2) ? koff : voff) + (size_t)(j0 + r) * (3 * EMB) + ch * 8;
            const char* src = (const char*)(((arr & 1) ? QKVl : QKVh) + goff);
            uint32_t dst = sKh + (uint32_t)arr * 8192u
                         + (uint32_t)(r * 128 + ((ch ^ (r & 7)) << 4));
            CP_ASYNC16(dst, src);
        }
        CP_COMMIT();
        CP_WAIT0();
        __syncthreads();

        // ---- S = Q @ K^T (split, 3 terms) ----
        float s[8][4];
#pragma unroll
        for (int nb = 0; nb < 8; nb++)
#pragma unroll
            for (int q = 0; q < 4; q++) s[nb][q] = 0.f;

#pragma unroll
        for (int kc = 0; kc < 4; kc++) {
            uint32_t aqh[4], aql[4];
            {
                int row = wid * 16 + (grp & 1) * 8 + l8;
                int ch  = 2 * kc + (grp >> 1);
                uint32_t sw = (uint32_t)(row * 128 + ((ch ^ (row & 7)) << 4));
                ldsm4(aqh, sQh + sw);
                ldsm4(aql, sQl + sw);
            }
#pragma unroll
            for (int ng = 0; ng < 4; ng++) {
                uint32_t kh[4], kl[4];
                int row = ng * 16 + (grp >> 1) * 8 + l8;
                int ch  = 2 * kc + (grp & 1);
                uint32_t sw = (uint32_t)(row * 128 + ((ch ^ (row & 7)) << 4));
                ldsm4(kh, sKh + sw);
                ldsm4(kl, sKh + 8192u + sw);
                mma16816(s[2 * ng],     aqh, kh[0], kh[1]);
                mma16816(s[2 * ng + 1], aqh, kh[2], kh[3]);
                mma16816(s[2 * ng],     aqh, kl[0], kl[1]);
                mma16816(s[2 * ng + 1], aqh, kl[2], kl[3]);
                mma16816(s[2 * ng],     aql, kh[0], kh[1]);
                mma16816(s[2 * ng + 1], aql, kh[2], kh[3]);
            }
        }

        // ---- online softmax (rows r = lane>>2 and r+8, quad-wide) ----
        float mx0 = -1e30f, mx1 = -1e30f;
#pragma unroll
        for (int nb = 0; nb < 8; nb++) {
#pragma unroll
            for (int q = 0; q < 4; q++) s[nb][q] *= 0.125f;
            mx0 = fmaxf(mx0, fmaxf(s[nb][0], s[nb][1]));
            mx1 = fmaxf(mx1, fmaxf(s[nb][2], s[nb][3]));
        }
        mx0 = fmaxf(mx0, __shfl_xor_sync(0xffffffffu, mx0, 1));
        mx0 = fmaxf(mx0, __shfl_xor_sync(0xffffffffu, mx0, 2));
        mx1 = fmaxf(mx1, __shfl_xor_sync(0xffffffffu, mx1, 1));
        mx1 = fmaxf(mx1, __shfl_xor_sync(0xffffffffu, mx1, 2));
        float mn0 = fmaxf(m0, mx0), mn1 = fmaxf(m1, mx1);
        float al0 = __expf(m0 - mn0), al1 = __expf(m1 - mn1);
        m0 = mn0; m1 = mn1;
        float rs0 = 0.f, rs1 = 0.f;
#pragma unroll
        for (int nb = 0; nb < 8; nb++) {
            s[nb][0] = __expf(s[nb][0] - mn0);
            s[nb][1] = __expf(s[nb][1] - mn0);
            s[nb][2] = __expf(s[nb][2] - mn1);
            s[nb][3] = __expf(s[nb][3] - mn1);
            rs0 += s[nb][0] + s[nb][1];
            rs1 += s[nb][2] + s[nb][3];
        }
        rs0 += __shfl_xor_sync(0xffffffffu, rs0, 1);
        rs0 += __shfl_xor_sync(0xffffffffu, rs0, 2);
        rs1 += __shfl_xor_sync(0xffffffffu, rs1, 1);
        rs1 += __shfl_xor_sync(0xffffffffu, rs1, 2);
        l0 = l0 * al0 + rs0;
        l1 = l1 * al1 + rs1;
#pragma unroll
        for (int d = 0; d < 8; d++) {
            o[d][0] *= al0; o[d][1] *= al0;
            o[d][2] *= al1; o[d][3] *= al1;
        }

        // ---- O += P @ V (split, 3 terms); P packed in-register ----
#pragma unroll
        for (int kc = 0; kc < 4; kc++) {
            uint32_t ph[4], pl[4];
            packsplit(s[2 * kc][0],     s[2 * kc][1],     ph[0], pl[0]);
            packsplit(s[2 * kc][2],     s[2 * kc][3],     ph[1], pl[1]);
            packsplit(s[2 * kc + 1][0], s[2 * kc + 1][1], ph[2], pl[2]);
            packsplit(s[2 * kc + 1][2], s[2 * kc + 1][3], ph[3], pl[3]);
#pragma unroll
            for (int dg = 0; dg < 4; dg++) {
                uint32_t vh[4], vl[4];
                int row = kc * 16 + (grp & 1) * 8 + l8;   // kv row
                int ch  = 2 * dg + (grp >> 1);            // d chunk
                uint32_t sw = (uint32_t)(row * 128 + ((ch ^ (row & 7)) << 4));
                ldsm4t(vh, sKh + 16384u + sw);
                ldsm4t(vl, sKh + 24576u + sw);
                mma16816(o[2 * dg],     ph, vh[0], vh[1]);
                mma16816(o[2 * dg + 1], ph, vh[2], vh[3]);
                mma16816(o[2 * dg],     ph, vl[0], vl[1]);
                mma16816(o[2 * dg + 1], ph, vl[2], vl[3]);
                mma16816(o[2 * dg],     pl, vh[0], vh[1]);
                mma16816(o[2 * dg + 1], pl, vh[2], vh[3]);
            }
        }
        __syncthreads();   // all smem reads done before next tile's loads
    }

    // epilogue: normalize, write bf16 hi/lo pairs to [M, E]
    float il0 = 1.f / l0, il1 = 1.f / l1;
    int rg0 = q0 + wid * 16 + (lane >> 2);
#pragma unroll
    for (int d = 0; d < 8; d++) {
        int col = h * HDIM + d * 8 + (lane & 3) * 2;
        size_t off0 = ((size_t)b * SEQ + rg0) * EMB + col;
        size_t off1 = ((size_t)b * SEQ + rg0 + 8) * EMB + col;
        uint32_t hi, lo;
        packsplit(o[d][0] * il0, o[d][1] * il0, hi, lo);
        *(uint32_t*)(Oh + off0) = hi;
        *(uint32_t*)(Ol + off0) = lo;
        packsplit(o[d][2] * il1, o[d][3] * il1, hi, lo);
        *(uint32_t*)(Oh + off1) = hi;
        *(uint32_t*)(Ol + off1) = lo;
    }
}

// ---------------------------------------------------------------------------
// Launch
// ---------------------------------------------------------------------------
extern "C" void kernel_launch(void* const* d_in, const int* in_sizes, int n_in,
                              void* d_out, int out_size)
{
    const float *x = nullptr, *Wqkv = nullptr, *bqkv = nullptr,
                *Wout = nullptr, *bout = nullptr;
    for (int i = 0; i < n_in; i++) {
        switch (in_sizes[i]) {
            case 4194304: x    = (const float*)d_in[i]; break;  // [2,2048,1024]
            case 3145728: Wqkv = (const float*)d_in[i]; break;  // [1024,3072]
            case 3072:    bqkv = (const float*)d_in[i]; break;
            case 1048576: Wout = (const float*)d_in[i]; break;  // [1024,1024]
            case 1024:    bout = (const float*)d_in[i]; break;
        }
    }
    float* out = (float*)d_out;

    __nv_bfloat16 *xh, *xl, *qkvh, *qkvl, *ah, *al, *wqh, *wql, *woh, *wol;
    cudaGetSymbolAddress((void**)&xh,   g_xh);
    cudaGetSymbolAddress((void**)&xl,   g_xl);
    cudaGetSymbolAddress((void**)&qkvh, g_qkvh);
    cudaGetSymbolAddress((void**)&qkvl, g_qkvl);
    cudaGetSymbolAddress((void**)&ah,   g_ah);
    cudaGetSymbolAddress((void**)&al,   g_al);
    cudaGetSymbolAddress((void**)&wqh,  g_wqh);
    cudaGetSymbolAddress((void**)&wql,  g_wql);
    cudaGetSymbolAddress((void**)&woh,  g_woh);
    cudaGetSymbolAddress((void**)&wol,  g_wol);

    cudaFuncSetAttribute(gemm_mma_kernel,
                         cudaFuncAttributeMaxDynamicSharedMemorySize, GEMM_SMEM);
    cudaFuncSetAttribute(flash_mma_kernel,
                         cudaFuncAttributeMaxDynamicSharedMemorySize, FLASH_SMEM);

    // 0a. split x -> bf16 hi/lo
    split_kernel<<<(MTOK * EMB / 4 + 255) / 256, 256>>>(x, xh, xl, MTOK * EMB / 4);
    // 0b. transpose + split weights
    {
        dim3 g1(3 * EMB / 32, EMB / 32);
        transpose_split_kernel<<<g1, dim3(32, 8)>>>(Wqkv, wqh, wql, EMB, 3 * EMB);
        dim3 g2(EMB / 32, EMB / 32);
        transpose_split_kernel<<<g2, dim3(32, 8)>>>(Wout, woh, wol, EMB, EMB);
    }
    // 1. QKV projection -> bf16 hi/lo qkv directly
    {
        dim3 grid(3 * EMB / 128, MTOK / 128);
        gemm_mma_kernel<<<grid, 256, GEMM_SMEM>>>(
            xh, xl, wqh, wql, bqkv, nullptr, qkvh, qkvl, MTOK, 3 * EMB, EMB);
    }
    // 2. Flash attention -> bf16 hi/lo attn output directly
    {
        dim3 grid(SEQ / 128, HEADS, BATCH);
        flash_mma_kernel<<<grid, 256, FLASH_SMEM>>>(qkvh, qkvl, ah, al);
    }
    // 3. Output projection -> fp32 final output
    {
        dim3 grid(EMB / 128, MTOK / 128);
        gemm_mma_kernel<<<grid, 256, GEMM_SMEM>>>(
            ah, al, woh, wol, bout, out, nullptr, nullptr, MTOK, EMB, EMB);
    }
}

// round 5
// speedup vs baseline: 3.1978x; 1.0991x over previous
#include <cuda_runtime.h>
#include <cuda_bf16.h>
#include <cstdint>

// Problem constants
#define BATCH 2
#define SEQ   2048
#define EMB   1024
#define HEADS 16
#define HDIM  64
#define MTOK  (BATCH * SEQ)        // 4096 tokens

// ---------------------------------------------------------------------------
// Scratch (allocation-free: device globals), all bf16 hi/lo pairs
// ---------------------------------------------------------------------------
__device__ __nv_bfloat16 g_xh[(size_t)MTOK * EMB],  g_xl[(size_t)MTOK * EMB];
__device__ __nv_bfloat16 g_qkvh[(size_t)MTOK * 3 * EMB], g_qkvl[(size_t)MTOK * 3 * EMB];
__device__ __nv_bfloat16 g_ah[(size_t)MTOK * EMB],  g_al[(size_t)MTOK * EMB];
__device__ __nv_bfloat16 g_wqh[(size_t)3 * EMB * EMB], g_wql[(size_t)3 * EMB * EMB]; // W_qkv^T [3E,E]
__device__ __nv_bfloat16 g_woh[(size_t)EMB * EMB],     g_wol[(size_t)EMB * EMB];     // W_out^T [E,E]

// ---------------------------------------------------------------------------
// Helpers: cp.async, ldmatrix, mma.sync (portable compute_100 PTX)
// ---------------------------------------------------------------------------
__device__ __forceinline__ uint32_t smem_u32(const void* p) {
    uint32_t a;
    asm("{ .reg .u64 t; cvta.to.shared.u64 t, %1; cvt.u32.u64 %0, t; }"
        : "=r"(a) : "l"(p));
    return a;
}
#define CP_ASYNC16(dst, src) \
    asm volatile("cp.async.cg.shared.global [%0], [%1], 16;" :: "r"(dst), "l"(src))
#define CP_COMMIT() asm volatile("cp.async.commit_group;" ::: "memory")
#define CP_WAIT0()  asm volatile("cp.async.wait_group 0;" ::: "memory")
#define CP_WAIT1()  asm volatile("cp.async.wait_group 1;" ::: "memory")
#define CP_WAIT2()  asm volatile("cp.async.wait_group 2;" ::: "memory")

__device__ __forceinline__ void ldsm4(uint32_t a[4], uint32_t addr) {
    asm volatile("ldmatrix.sync.aligned.m8n8.x4.shared.b16 {%0,%1,%2,%3}, [%4];"
        : "=r"(a[0]), "=r"(a[1]), "=r"(a[2]), "=r"(a[3]) : "r"(addr));
}
__device__ __forceinline__ void ldsm4t(uint32_t a[4], uint32_t addr) {
    asm volatile("ldmatrix.sync.aligned.m8n8.x4.trans.shared.b16 {%0,%1,%2,%3}, [%4];"
        : "=r"(a[0]), "=r"(a[1]), "=r"(a[2]), "=r"(a[3]) : "r"(addr));
}
__device__ __forceinline__ void mma16816(float c[4], const uint32_t a[4],
                                         uint32_t b0, uint32_t b1) {
    asm volatile("mma.sync.aligned.m16n8k16.row.col.f32.bf16.bf16.f32 "
                 "{%0,%1,%2,%3}, {%4,%5,%6,%7}, {%8,%9}, {%0,%1,%2,%3};"
                 : "+f"(c[0]), "+f"(c[1]), "+f"(c[2]), "+f"(c[3])
                 : "r"(a[0]), "r"(a[1]), "r"(a[2]), "r"(a[3]), "r"(b0), "r"(b1));
}

__device__ __forceinline__ void packsplit(float x, float y,
                                          uint32_t& hi, uint32_t& lo) {
    __nv_bfloat16 hx = __float2bfloat16_rn(x);
    __nv_bfloat16 hy = __float2bfloat16_rn(y);
    __nv_bfloat162 h2(hx, hy);
    hi = *reinterpret_cast<uint32_t*>(&h2);
    __nv_bfloat16 lx = __float2bfloat16_rn(x - __bfloat162float(hx));
    __nv_bfloat16 ly = __float2bfloat16_rn(y - __bfloat162float(hy));
    __nv_bfloat162 l2(lx, ly);
    lo = *reinterpret_cast<uint32_t*>(&l2);
}

// ---------------------------------------------------------------------------
// Conversion kernels
// ---------------------------------------------------------------------------
__global__ __launch_bounds__(256) void split_kernel(
    const float* __restrict__ in, __nv_bfloat16* __restrict__ hi,
    __nv_bfloat16* __restrict__ lo, int n4)
{
    int i = blockIdx.x * blockDim.x + threadIdx.x;
    if (i >= n4) return;
    float4 v = ((const float4*)in)[i];
    uint32_t h0, l0, h1, l1;
    packsplit(v.x, v.y, h0, l0);
    packsplit(v.z, v.w, h1, l1);
    ((uint32_t*)hi)[i * 2]     = h0;
    ((uint32_t*)hi)[i * 2 + 1] = h1;
    ((uint32_t*)lo)[i * 2]     = l0;
    ((uint32_t*)lo)[i * 2 + 1] = l1;
}

// W[K,N] -> T_hi/T_lo [N,K]
__global__ __launch_bounds__(256) void transpose_split_kernel(
    const float* __restrict__ W, __nv_bfloat16* __restrict__ Th,
    __nv_bfloat16* __restrict__ Tl, int K, int N)
{
    __shared__ float t[32][33];
    int n0 = blockIdx.x * 32, k0 = blockIdx.y * 32;
#pragma unroll
    for (int r = threadIdx.y; r < 32; r += 8)
        t[r][threadIdx.x] = W[(size_t)(k0 + r) * N + n0 + threadIdx.x];
    __syncthreads();
#pragma unroll
    for (int r = threadIdx.y; r < 32; r += 8) {
        float v = t[threadIdx.x][r];          // W[k0+tx][n0+r]
        __nv_bfloat16 h = __float2bfloat16_rn(v);
        __nv_bfloat16 l = __float2bfloat16_rn(v - __bfloat162float(h));
        size_t o = (size_t)(n0 + r) * K + k0 + threadIdx.x;
        Th[o] = h;
        Tl[o] = l;
    }
}

// ---------------------------------------------------------------------------
// Split-bf16 GEMM via mma.sync: C[M,N] = (Ah+Al)[M,K] @ (Bh+Bl)[N,K]^T + bias
// Virtual K-extension phases (Ah,Bh), (Al,Bh), (Ah,Bl).
// Tile 128x128, BK=64, 3-stage cp.async pipeline, 2 CTAs/SM.
// ---------------------------------------------------------------------------
#define GSTAGE 32768
#define GEMM_SMEM (3 * GSTAGE)     // 96 KB

__global__ __launch_bounds__(256, 2) void gemm_mma_kernel(
    const __nv_bfloat16* __restrict__ Ah, const __nv_bfloat16* __restrict__ Al,
    const __nv_bfloat16* __restrict__ Bh, const __nv_bfloat16* __restrict__ Bl,
    const float* __restrict__ bias,
    float* __restrict__ Cf,
    __nv_bfloat16* __restrict__ Ch, __nv_bfloat16* __restrict__ Cl,
    int M, int N, int K)
{
    extern __shared__ char smem[];
    uint32_t sbase = smem_u32(smem);

    const int tid  = threadIdx.x;
    const int lane = tid & 31;
    const int wid  = tid >> 5;
    const int wm   = wid >> 1;
    const int wn   = wid & 1;
    const int row0 = blockIdx.y * 128;
    const int col0 = blockIdx.x * 128;
    const int KC   = K >> 6;           // 64-wide chunks per phase
    const int NST  = 3 * KC;
    const int grp  = lane >> 3, l8 = lane & 7;

    float c[2][8][4];
#pragma unroll
    for (int mb = 0; mb < 2; mb++)
#pragma unroll
        for (int nb = 0; nb < 8; nb++)
#pragma unroll
            for (int q = 0; q < 4; q++) c[mb][nb][q] = 0.f;

    auto load_stage = [&](int s, int buf) {
        int ph = s >= 2 * KC ? 2 : (s >= KC ? 1 : 0);
        int k0 = (s - ph * KC) << 6;
        const __nv_bfloat16* ap = (ph == 1) ? Al : Ah;
        const __nv_bfloat16* bp = (ph == 2) ? Bl : Bh;
        const char* ab = (const char*)(ap + (size_t)row0 * K + k0);
        const char* bb = (const char*)(bp + (size_t)col0 * K + k0);
        uint32_t dstb = sbase + (uint32_t)buf * (uint32_t)GSTAGE;
#pragma unroll
        for (int it = 0; it < 8; it++) {
            int cch = tid + it * 256;       // 0..2047
            int arr = cch >> 10;            // 0 = A, 1 = B
            int cc  = cch & 1023;
            int r   = cc >> 3, ch = cc & 7;
            const char* src = (arr ? bb : ab) + (size_t)r * (K * 2) + ch * 16;
            uint32_t dst = dstb + (uint32_t)arr * 16384u
                         + (uint32_t)(r * 128 + ((ch ^ (r & 7)) << 4));
            CP_ASYNC16(dst, src);
        }
    };

    load_stage(0, 0);
    CP_COMMIT();
    load_stage(1, 1);
    CP_COMMIT();

    for (int s = 0; s < NST; s++) {
        int buf = s % 3;
        if (s + 2 < NST) {
            load_stage(s + 2, (s + 2) % 3);
            CP_COMMIT();
            CP_WAIT2();
        } else if (s + 1 < NST) {
            CP_WAIT1();
        } else {
            CP_WAIT0();
        }
        __syncthreads();

        uint32_t abase = sbase + (uint32_t)buf * (uint32_t)GSTAGE;
        uint32_t bbase = abase + 16384u;
#pragma unroll
        for (int kc = 0; kc < 4; kc++) {
            uint32_t afr[2][4];
#pragma unroll
            for (int mb = 0; mb < 2; mb++) {
                int row = wm * 32 + mb * 16 + (grp & 1) * 8 + l8;
                int ch  = 2 * kc + (grp >> 1);
                ldsm4(afr[mb], abase + row * 128 + ((ch ^ (row & 7)) << 4));
            }
#pragma unroll
            for (int ng = 0; ng < 4; ng++) {
                uint32_t bfr[4];
                int row = wn * 64 + ng * 16 + (grp >> 1) * 8 + l8;
                int ch  = 2 * kc + (grp & 1);
                ldsm4(bfr, bbase + row * 128 + ((ch ^ (row & 7)) << 4));
#pragma unroll
                for (int mb = 0; mb < 2; mb++) {
                    mma16816(c[mb][2 * ng],     afr[mb], bfr[0], bfr[1]);
                    mma16816(c[mb][2 * ng + 1], afr[mb], bfr[2], bfr[3]);
                }
            }
        }
        __syncthreads();
    }

    // epilogue
#pragma unroll
    for (int mb = 0; mb < 2; mb++) {
#pragma unroll
        for (int half = 0; half < 2; half++) {
            int row = row0 + wm * 32 + mb * 16 + (lane >> 2) + half * 8;
#pragma unroll
            for (int nb = 0; nb < 8; nb++) {
                int col = col0 + wn * 64 + nb * 8 + (lane & 3) * 2;
                float v0 = c[mb][nb][2 * half]     + bias[col];
                float v1 = c[mb][nb][2 * half + 1] + bias[col + 1];
                size_t off = (size_t)row * N + col;
                if (Cf) {
                    float2 o = make_float2(v0, v1);
                    *(float2*)(Cf + off) = o;
                } else {
                    uint32_t hi, lo;
                    packsplit(v0, v1, hi, lo);
                    *(uint32_t*)(Ch + off) = hi;
                    *(uint32_t*)(Cl + off) = lo;
                }
            }
        }
    }
}

// ---------------------------------------------------------------------------
// Flash attention via mma.sync, split-bf16 QK and PV.
// CTA: 256 thr (8 warps), BQ=128, BKV=64, 2-stage KV prefetch, 2 CTAs/SM.
// smem: Qh,Ql (16KB ea) + 2 KV stages (32KB ea: Kh,Kl,Vh,Vl x 8KB) = 96KB.
// ---------------------------------------------------------------------------
#define KVSTAGE 32768
#define FLASH_SMEM (32768 + 2 * KVSTAGE)   // 96 KB

__global__ __launch_bounds__(256, 2) void flash_mma_kernel(
    const __nv_bfloat16* __restrict__ QKVh, const __nv_bfloat16* __restrict__ QKVl,
    __nv_bfloat16* __restrict__ Oh, __nv_bfloat16* __restrict__ Ol)
{
    extern __shared__ char smem[];
    uint32_t sb  = smem_u32(smem);
    uint32_t sQh = sb, sQl = sb + 16384;
    uint32_t sKV = sb + 32768;      // + buf*KVSTAGE; inside: Kh 0, Kl 8K, Vh 16K, Vl 24K

    const int tid  = threadIdx.x;
    const int lane = tid & 31;
    const int wid  = tid >> 5;
    const int grp  = lane >> 3, l8 = lane & 7;
    const int q0   = blockIdx.x * 128;
    const int h    = blockIdx.y;
    const int b    = blockIdx.z;

    const size_t qoff = ((size_t)b * SEQ + q0) * (3 * EMB) + h * HDIM;
    const size_t koff = ((size_t)b * SEQ) * (3 * EMB) + h * HDIM + EMB;
    const size_t voff = koff + EMB;

    auto load_kv = [&](int j0, int buf) {
        uint32_t dstb = sKV + (uint32_t)buf * (uint32_t)KVSTAGE;
#pragma unroll
        for (int it = 0; it < 8; it++) {
            int cch = tid + it * 256;
            int arr = cch >> 9;              // 0 Kh, 1 Kl, 2 Vh, 3 Vl
            int cc  = cch & 511;
            int r   = cc >> 3, ch = cc & 7;
            size_t goff = ((arr < 2) ? koff : voff)
                        + (size_t)(j0 + r) * (3 * EMB) + ch * 8;
            const char* src = (const char*)(((arr & 1) ? QKVl : QKVh) + goff);
            uint32_t dst = dstb + (uint32_t)arr * 8192u
                         + (uint32_t)(r * 128 + ((ch ^ (r & 7)) << 4));
            CP_ASYNC16(dst, src);
        }
    };

    // prologue: Q tiles + KV stage 0 -> group 0 ; KV stage 1 -> group 1
#pragma unroll
    for (int it = 0; it < 8; it++) {
        int cch = tid + it * 256;
        int arr = cch >> 10;
        int cc  = cch & 1023;
        int r   = cc >> 3, ch = cc & 7;
        const char* src = (const char*)((arr ? QKVl : QKVh) + qoff
                                        + (size_t)r * (3 * EMB) + ch * 8);
        uint32_t dst = (arr ? sQl : sQh)
                     + (uint32_t)(r * 128 + ((ch ^ (r & 7)) << 4));
        CP_ASYNC16(dst, src);
    }
    load_kv(0, 0);
    CP_COMMIT();
    load_kv(64, 1);
    CP_COMMIT();

    float m0 = -1e30f, m1 = -1e30f, l0 = 0.f, l1 = 0.f;
    float o[8][4];
#pragma unroll
    for (int d = 0; d < 8; d++)
#pragma unroll
        for (int q = 0; q < 4; q++) o[d][q] = 0.f;

    const int NKV = SEQ / 64;
    for (int jt = 0; jt < NKV; jt++) {
        int buf = jt & 1;
        if (jt + 1 < NKV) CP_WAIT1(); else CP_WAIT0();
        __syncthreads();

        uint32_t kb = sKV + (uint32_t)buf * (uint32_t)KVSTAGE;

        // ---- S = Q @ K^T (split, 3 terms) ----
        float s[8][4];
#pragma unroll
        for (int nb = 0; nb < 8; nb++)
#pragma unroll
            for (int q = 0; q < 4; q++) s[nb][q] = 0.f;

#pragma unroll
        for (int kc = 0; kc < 4; kc++) {
            uint32_t aqh[4], aql[4];
            {
                int row = wid * 16 + (grp & 1) * 8 + l8;
                int ch  = 2 * kc + (grp >> 1);
                uint32_t sw = (uint32_t)(row * 128 + ((ch ^ (row & 7)) << 4));
                ldsm4(aqh, sQh + sw);
                ldsm4(aql, sQl + sw);
            }
#pragma unroll
            for (int ng = 0; ng < 4; ng++) {
                uint32_t kh[4], kl[4];
                int row = ng * 16 + (grp >> 1) * 8 + l8;
                int ch  = 2 * kc + (grp & 1);
                uint32_t sw = (uint32_t)(row * 128 + ((ch ^ (row & 7)) << 4));
                ldsm4(kh, kb + sw);
                ldsm4(kl, kb + 8192u + sw);
                mma16816(s[2 * ng],     aqh, kh[0], kh[1]);
                mma16816(s[2 * ng + 1], aqh, kh[2], kh[3]);
                mma16816(s[2 * ng],     aqh, kl[0], kl[1]);
                mma16816(s[2 * ng + 1], aqh, kl[2], kl[3]);
                mma16816(s[2 * ng],     aql, kh[0], kh[1]);
                mma16816(s[2 * ng + 1], aql, kh[2], kh[3]);
            }
        }

        // ---- online softmax (rows r = lane>>2 and r+8, quad-wide) ----
        float mx0 = -1e30f, mx1 = -1e30f;
#pragma unroll
        for (int nb = 0; nb < 8; nb++) {
#pragma unroll
            for (int q = 0; q < 4; q++) s[nb][q] *= 0.125f;
            mx0 = fmaxf(mx0, fmaxf(s[nb][0], s[nb][1]));
            mx1 = fmaxf(mx1, fmaxf(s[nb][2], s[nb][3]));
        }
        mx0 = fmaxf(mx0, __shfl_xor_sync(0xffffffffu, mx0, 1));
        mx0 = fmaxf(mx0, __shfl_xor_sync(0xffffffffu, mx0, 2));
        mx1 = fmaxf(mx1, __shfl_xor_sync(0xffffffffu, mx1, 1));
        mx1 = fmaxf(mx1, __shfl_xor_sync(0xffffffffu, mx1, 2));
        float mn0 = fmaxf(m0, mx0), mn1 = fmaxf(m1, mx1);
        float al0 = __expf(m0 - mn0), al1 = __expf(m1 - mn1);
        m0 = mn0; m1 = mn1;
        float rs0 = 0.f, rs1 = 0.f;
#pragma unroll
        for (int nb = 0; nb < 8; nb++) {
            s[nb][0] = __expf(s[nb][0] - mn0);
            s[nb][1] = __expf(s[nb][1] - mn0);
            s[nb][2] = __expf(s[nb][2] - mn1);
            s[nb][3] = __expf(s[nb][3] - mn1);
            rs0 += s[nb][0] + s[nb][1];
            rs1 += s[nb][2] + s[nb][3];
        }
        rs0 += __shfl_xor_sync(0xffffffffu, rs0, 1);
        rs0 += __shfl_xor_sync(0xffffffffu, rs0, 2);
        rs1 += __shfl_xor_sync(0xffffffffu, rs1, 1);
        rs1 += __shfl_xor_sync(0xffffffffu, rs1, 2);
        l0 = l0 * al0 + rs0;
        l1 = l1 * al1 + rs1;
#pragma unroll
        for (int d = 0; d < 8; d++) {
            o[d][0] *= al0; o[d][1] *= al0;
            o[d][2] *= al1; o[d][3] *= al1;
        }

        // ---- O += P @ V (split, 3 terms); P packed in-register ----
#pragma unroll
        for (int kc = 0; kc < 4; kc++) {
            uint32_t ph[4], pl[4];
            packsplit(s[2 * kc][0],     s[2 * kc][1],     ph[0], pl[0]);
            packsplit(s[2 * kc][2],     s[2 * kc][3],     ph[1], pl[1]);
            packsplit(s[2 * kc + 1][0], s[2 * kc + 1][1], ph[2], pl[2]);
            packsplit(s[2 * kc + 1][2], s[2 * kc + 1][3], ph[3], pl[3]);
#pragma unroll
            for (int dg = 0; dg < 4; dg++) {
                uint32_t vh[4], vl[4];
                int row = kc * 16 + (grp & 1) * 8 + l8;   // kv row
                int ch  = 2 * dg + (grp >> 1);            // d chunk
                uint32_t sw = (uint32_t)(row * 128 + ((ch ^ (row & 7)) << 4));
                ldsm4t(vh, kb + 16384u + sw);
                ldsm4t(vl, kb + 24576u + sw);
                mma16816(o[2 * dg],     ph, vh[0], vh[1]);
                mma16816(o[2 * dg + 1], ph, vh[2], vh[3]);
                mma16816(o[2 * dg],     ph, vl[0], vl[1]);
                mma16816(o[2 * dg + 1], ph, vl[2], vl[3]);
                mma16816(o[2 * dg],     pl, vh[0], vh[1]);
                mma16816(o[2 * dg + 1], pl, vh[2], vh[3]);
            }
        }
        __syncthreads();   // all reads of buf done before refilling it

        if (jt + 2 < NKV) {
            load_kv((jt + 2) * 64, buf);
            CP_COMMIT();
        }
    }

    // epilogue: normalize, write bf16 hi/lo pairs to [M, E]
    float il0 = 1.f / l0, il1 = 1.f / l1;
    int rg0 = q0 + wid * 16 + (lane >> 2);
#pragma unroll
    for (int d = 0; d < 8; d++) {
        int col = h * HDIM + d * 8 + (lane & 3) * 2;
        size_t off0 = ((size_t)b * SEQ + rg0) * EMB + col;
        size_t off1 = ((size_t)b * SEQ + rg0 + 8) * EMB + col;
        uint32_t hi, lo;
        packsplit(o[d][0] * il0, o[d][1] * il0, hi, lo);
        *(uint32_t*)(Oh + off0) = hi;
        *(uint32_t*)(Ol + off0) = lo;
        packsplit(o[d][2] * il1, o[d][3] * il1, hi, lo);
        *(uint32_t*)(Oh + off1) = hi;
        *(uint32_t*)(Ol + off1) = lo;
    }
}

// ---------------------------------------------------------------------------
// Launch
// ---------------------------------------------------------------------------
extern "C" void kernel_launch(void* const* d_in, const int* in_sizes, int n_in,
                              void* d_out, int out_size)
{
    const float *x = nullptr, *Wqkv = nullptr, *bqkv = nullptr,
                *Wout = nullptr, *bout = nullptr;
    for (int i = 0; i < n_in; i++) {
        switch (in_sizes[i]) {
            case 4194304: x    = (const float*)d_in[i]; break;  // [2,2048,1024]
            case 3145728: Wqkv = (const float*)d_in[i]; break;  // [1024,3072]
            case 3072:    bqkv = (const float*)d_in[i]; break;
            case 1048576: Wout = (const float*)d_in[i]; break;  // [1024,1024]
            case 1024:    bout = (const float*)d_in[i]; break;
        }
    }
    float* out = (float*)d_out;

    __nv_bfloat16 *xh, *xl, *qkvh, *qkvl, *ah, *al, *wqh, *wql, *woh, *wol;
    cudaGetSymbolAddress((void**)&xh,   g_xh);
    cudaGetSymbolAddress((void**)&xl,   g_xl);
    cudaGetSymbolAddress((void**)&qkvh, g_qkvh);
    cudaGetSymbolAddress((void**)&qkvl, g_qkvl);
    cudaGetSymbolAddress((void**)&ah,   g_ah);
    cudaGetSymbolAddress((void**)&al,   g_al);
    cudaGetSymbolAddress((void**)&wqh,  g_wqh);
    cudaGetSymbolAddress((void**)&wql,  g_wql);
    cudaGetSymbolAddress((void**)&woh,  g_woh);
    cudaGetSymbolAddress((void**)&wol,  g_wol);

    cudaFuncSetAttribute(gemm_mma_kernel,
                         cudaFuncAttributeMaxDynamicSharedMemorySize, GEMM_SMEM);
    cudaFuncSetAttribute(flash_mma_kernel,
                         cudaFuncAttributeMaxDynamicSharedMemorySize, FLASH_SMEM);

    // 0a. split x -> bf16 hi/lo
    split_kernel<<<(MTOK * EMB / 4 + 255) / 256, 256>>>(x, xh, xl, MTOK * EMB / 4);
    // 0b. transpose + split weights
    {
        dim3 g1(3 * EMB / 32, EMB / 32);
        transpose_split_kernel<<<g1, dim3(32, 8)>>>(Wqkv, wqh, wql, EMB, 3 * EMB);
        dim3 g2(EMB / 32, EMB / 32);
        transpose_split_kernel<<<g2, dim3(32, 8)>>>(Wout, woh, wol, EMB, EMB);
    }
    // 1. QKV projection -> bf16 hi/lo qkv directly
    {
        dim3 grid(3 * EMB / 128, MTOK / 128);
        gemm_mma_kernel<<<grid, 256, GEMM_SMEM>>>(
            xh, xl, wqh, wql, bqkv, nullptr, qkvh, qkvl, MTOK, 3 * EMB, EMB);
    }
    // 2. Flash attention -> bf16 hi/lo attn output directly
    {
        dim3 grid(SEQ / 128, HEADS, BATCH);
        flash_mma_kernel<<<grid, 256, FLASH_SMEM>>>(qkvh, qkvl, ah, al);
    }
    // 3. Output projection -> fp32 final output
    {
        dim3 grid(EMB / 128, MTOK / 128);
        gemm_mma_kernel<<<grid, 256, GEMM_SMEM>>>(
            ah, al, woh, wol, bout, out, nullptr, nullptr, MTOK, EMB, EMB);
    }
}

// round 7
// speedup vs baseline: 3.2097x; 1.0037x over previous
#include <cuda_runtime.h>
#include <cuda_bf16.h>
#include <cstdint>

// Problem constants
#define BATCH 2
#define SEQ   2048
#define EMB   1024
#define HEADS 16
#define HDIM  64
#define MTOK  (BATCH * SEQ)        // 4096 tokens

// ---------------------------------------------------------------------------
// Scratch (allocation-free: device globals), all bf16 hi/lo pairs
// ---------------------------------------------------------------------------
__device__ __nv_bfloat16 g_xh[(size_t)MTOK * EMB],  g_xl[(size_t)MTOK * EMB];
__device__ __nv_bfloat16 g_qkvh[(size_t)MTOK * 3 * EMB], g_qkvl[(size_t)MTOK * 3 * EMB];
__device__ __nv_bfloat16 g_ah[(size_t)MTOK * EMB],  g_al[(size_t)MTOK * EMB];
__device__ __nv_bfloat16 g_wqh[(size_t)3 * EMB * EMB], g_wql[(size_t)3 * EMB * EMB]; // W_qkv^T [3E,E]
__device__ __nv_bfloat16 g_woh[(size_t)EMB * EMB],     g_wol[(size_t)EMB * EMB];     // W_out^T [E,E]

// ---------------------------------------------------------------------------
// Helpers: cp.async, ldmatrix, mma.sync (portable compute_100 PTX)
// ---------------------------------------------------------------------------
__device__ __forceinline__ uint32_t smem_u32(const void* p) {
    uint32_t a;
    asm("{ .reg .u64 t; cvta.to.shared.u64 t, %1; cvt.u32.u64 %0, t; }"
        : "=r"(a) : "l"(p));
    return a;
}
#define CP_ASYNC16(dst, src) \
    asm volatile("cp.async.cg.shared.global [%0], [%1], 16;" :: "r"(dst), "l"(src))
#define CP_COMMIT() asm volatile("cp.async.commit_group;" ::: "memory")
#define CP_WAIT0()  asm volatile("cp.async.wait_group 0;" ::: "memory")
#define CP_WAIT1()  asm volatile("cp.async.wait_group 1;" ::: "memory")
#define CP_WAIT2()  asm volatile("cp.async.wait_group 2;" ::: "memory")

__device__ __forceinline__ void ldsm4(uint32_t a[4], uint32_t addr) {
    asm volatile("ldmatrix.sync.aligned.m8n8.x4.shared.b16 {%0,%1,%2,%3}, [%4];"
        : "=r"(a[0]), "=r"(a[1]), "=r"(a[2]), "=r"(a[3]) : "r"(addr));
}
__device__ __forceinline__ void ldsm4t(uint32_t a[4], uint32_t addr) {
    asm volatile("ldmatrix.sync.aligned.m8n8.x4.trans.shared.b16 {%0,%1,%2,%3}, [%4];"
        : "=r"(a[0]), "=r"(a[1]), "=r"(a[2]), "=r"(a[3]) : "r"(addr));
}
__device__ __forceinline__ void mma16816(float c[4], const uint32_t a[4],
                                         uint32_t b0, uint32_t b1) {
    asm volatile("mma.sync.aligned.m16n8k16.row.col.f32.bf16.bf16.f32 "
                 "{%0,%1,%2,%3}, {%4,%5,%6,%7}, {%8,%9}, {%0,%1,%2,%3};"
                 : "+f"(c[0]), "+f"(c[1]), "+f"(c[2]), "+f"(c[3])
                 : "r"(a[0]), "r"(a[1]), "r"(a[2]), "r"(a[3]), "r"(b0), "r"(b1));
}

__device__ __forceinline__ void packsplit(float x, float y,
                                          uint32_t& hi, uint32_t& lo) {
    __nv_bfloat16 hx = __float2bfloat16_rn(x);
    __nv_bfloat16 hy = __float2bfloat16_rn(y);
    __nv_bfloat162 h2(hx, hy);
    hi = *reinterpret_cast<uint32_t*>(&h2);
    __nv_bfloat16 lx = __float2bfloat16_rn(x - __bfloat162float(hx));
    __nv_bfloat16 ly = __float2bfloat16_rn(y - __bfloat162float(hy));
    __nv_bfloat162 l2(lx, ly);
    lo = *reinterpret_cast<uint32_t*>(&l2);
}

// ---------------------------------------------------------------------------
// Conversion kernels
// ---------------------------------------------------------------------------
__global__ __launch_bounds__(256) void split_kernel(
    const float* __restrict__ in, __nv_bfloat16* __restrict__ hi,
    __nv_bfloat16* __restrict__ lo, int n4)
{
    int i = blockIdx.x * blockDim.x + threadIdx.x;
    if (i >= n4) return;
    float4 v = ((const float4*)in)[i];
    uint32_t h0, l0, h1, l1;
    packsplit(v.x, v.y, h0, l0);
    packsplit(v.z, v.w, h1, l1);
    ((uint32_t*)hi)[i * 2]     = h0;
    ((uint32_t*)hi)[i * 2 + 1] = h1;
    ((uint32_t*)lo)[i * 2]     = l0;
    ((uint32_t*)lo)[i * 2 + 1] = l1;
}

// W[K,N] -> T_hi/T_lo [N,K]
__global__ __launch_bounds__(256) void transpose_split_kernel(
    const float* __restrict__ W, __nv_bfloat16* __restrict__ Th,
    __nv_bfloat16* __restrict__ Tl, int K, int N)
{
    __shared__ float t[32][33];
    int n0 = blockIdx.x * 32, k0 = blockIdx.y * 32;
#pragma unroll
    for (int r = threadIdx.y; r < 32; r += 8)
        t[r][threadIdx.x] = W[(size_t)(k0 + r) * N + n0 + threadIdx.x];
    __syncthreads();
#pragma unroll
    for (int r = threadIdx.y; r < 32; r += 8) {
        float v = t[threadIdx.x][r];          // W[k0+tx][n0+r]
        __nv_bfloat16 h = __float2bfloat16_rn(v);
        __nv_bfloat16 l = __float2bfloat16_rn(v - __bfloat162float(h));
        size_t o = (size_t)(n0 + r) * K + k0 + threadIdx.x;
        Th[o] = h;
        Tl[o] = l;
    }
}

// ---------------------------------------------------------------------------
// Split-bf16 GEMM via mma.sync: C[M,N] = (Ah+Al)[M,K] @ (Bh+Bl)[N,K]^T + bias
// Virtual K-extension phases (Ah,Bh), (Al,Bh), (Ah,Bl).
// Tile 128x128, BK=64, 3-stage cp.async pipeline, ONE barrier per stage,
// 2 CTAs/SM.
// ---------------------------------------------------------------------------
#define GSTAGE 32768
#define GEMM_SMEM (3 * GSTAGE)     // 96 KB

__global__ __launch_bounds__(256, 2) void gemm_mma_kernel(
    const __nv_bfloat16* __restrict__ Ah, const __nv_bfloat16* __restrict__ Al,
    const __nv_bfloat16* __restrict__ Bh, const __nv_bfloat16* __restrict__ Bl,
    const float* __restrict__ bias,
    float* __restrict__ Cf,
    __nv_bfloat16* __restrict__ Ch, __nv_bfloat16* __restrict__ Cl,
    int M, int N, int K)
{
    extern __shared__ char smem[];
    uint32_t sbase = smem_u32(smem);

    const int tid  = threadIdx.x;
    const int lane = tid & 31;
    const int wid  = tid >> 5;
    const int wm   = wid >> 1;
    const int wn   = wid & 1;
    const int row0 = blockIdx.y * 128;
    const int col0 = blockIdx.x * 128;
    const int KC   = K >> 6;           // 64-wide chunks per phase
    const int NST  = 3 * KC;
    const int grp  = lane >> 3, l8 = lane & 7;

    float c[2][8][4];
#pragma unroll
    for (int mb = 0; mb < 2; mb++)
#pragma unroll
        for (int nb = 0; nb < 8; nb++)
#pragma unroll
            for (int q = 0; q < 4; q++) c[mb][nb][q] = 0.f;

    auto load_stage = [&](int s, int buf) {
        int ph = s >= 2 * KC ? 2 : (s >= KC ? 1 : 0);
        int k0 = (s - ph * KC) << 6;
        const __nv_bfloat16* ap = (ph == 1) ? Al : Ah;
        const __nv_bfloat16* bp = (ph == 2) ? Bl : Bh;
        const char* ab = (const char*)(ap + (size_t)row0 * K + k0);
        const char* bb = (const char*)(bp + (size_t)col0 * K + k0);
        uint32_t dstb = sbase + (uint32_t)buf * (uint32_t)GSTAGE;
#pragma unroll
        for (int it = 0; it < 8; it++) {
            int cch = tid + it * 256;       // 0..2047
            int arr = cch >> 10;            // 0 = A, 1 = B
            int cc  = cch & 1023;
            int r   = cc >> 3, ch = cc & 7;
            const char* src = (arr ? bb : ab) + (size_t)r * (K * 2) + ch * 16;
            uint32_t dst = dstb + (uint32_t)arr * 16384u
                         + (uint32_t)(r * 128 + ((ch ^ (r & 7)) << 4));
            CP_ASYNC16(dst, src);
        }
    };

    load_stage(0, 0);
    CP_COMMIT();
    load_stage(1, 1);
    CP_COMMIT();

    for (int s = 0; s < NST; s++) {
        int buf = s % 3;
        if (s + 1 < NST) CP_WAIT1(); else CP_WAIT0();
        __syncthreads();
        // buffer (s+2)%3 == (s-1)%3 was last read at stage s-1; the barrier
        // above guarantees all warps are past it.
        if (s + 2 < NST) {
            load_stage(s + 2, (s + 2) % 3);
            CP_COMMIT();
        }

        uint32_t abase = sbase + (uint32_t)buf * (uint32_t)GSTAGE;
        uint32_t bbase = abase + 16384u;
#pragma unroll
        for (int kc = 0; kc < 4; kc++) {
            uint32_t afr[2][4];
#pragma unroll
            for (int mb = 0; mb < 2; mb++) {
                int row = wm * 32 + mb * 16 + (grp & 1) * 8 + l8;
                int ch  = 2 * kc + (grp >> 1);
                ldsm4(afr[mb], abase + row * 128 + ((ch ^ (row & 7)) << 4));
            }
#pragma unroll
            for (int ng = 0; ng < 4; ng++) {
                uint32_t bfr[4];
                int row = wn * 64 + ng * 16 + (grp >> 1) * 8 + l8;
                int ch  = 2 * kc + (grp & 1);
                ldsm4(bfr, bbase + row * 128 + ((ch ^ (row & 7)) << 4));
#pragma unroll
                for (int mb = 0; mb < 2; mb++) {
                    mma16816(c[mb][2 * ng],     afr[mb], bfr[0], bfr[1]);
                    mma16816(c[mb][2 * ng + 1], afr[mb], bfr[2], bfr[3]);
                }
            }
        }
    }

    // epilogue (register-only sources; no barrier needed)
#pragma unroll
    for (int mb = 0; mb < 2; mb++) {
#pragma unroll
        for (int half = 0; half < 2; half++) {
            int row = row0 + wm * 32 + mb * 16 + (lane >> 2) + half * 8;
#pragma unroll
            for (int nb = 0; nb < 8; nb++) {
                int col = col0 + wn * 64 + nb * 8 + (lane & 3) * 2;
                float v0 = c[mb][nb][2 * half]     + bias[col];
                float v1 = c[mb][nb][2 * half + 1] + bias[col + 1];
                size_t off = (size_t)row * N + col;
                if (Cf) {
                    float2 o = make_float2(v0, v1);
                    *(float2*)(Cf + off) = o;
                } else {
                    uint32_t hi, lo;
                    packsplit(v0, v1, hi, lo);
                    *(uint32_t*)(Ch + off) = hi;
                    *(uint32_t*)(Cl + off) = lo;
                }
            }
        }
    }
}

// ---------------------------------------------------------------------------
// Flash attention via mma.sync, split-bf16 QK and PV.
// CTA: 256 thr (8 warps), BQ=128, BKV=64.
// Q fragments loaded ONCE into registers; the Q smem slot is then recycled as
// the 3rd KV stage -> 3-stage KV pipeline with ONE barrier per tile.
// smem: 3 x 32KB slots (slot layout: Kh 0 | Kl 8K | Vh 16K | Vl 24K).
// 2 CTAs/SM.
// ---------------------------------------------------------------------------
#define KVSTAGE 32768
#define FLASH_SMEM (3 * KVSTAGE)   // 96 KB

__global__ __launch_bounds__(256, 2) void flash_mma_kernel(
    const __nv_bfloat16* __restrict__ QKVh, const __nv_bfloat16* __restrict__ QKVl,
    __nv_bfloat16* __restrict__ Oh, __nv_bfloat16* __restrict__ Ol)
{
    extern __shared__ char smem[];
    uint32_t sb = smem_u32(smem);

    const int tid  = threadIdx.x;
    const int lane = tid & 31;
    const int wid  = tid >> 5;
    const int grp  = lane >> 3, l8 = lane & 7;
    const int q0   = blockIdx.x * 128;
    const int h    = blockIdx.y;
    const int b    = blockIdx.z;

    const size_t qoff = ((size_t)b * SEQ + q0) * (3 * EMB) + h * HDIM;
    const size_t koff = ((size_t)b * SEQ) * (3 * EMB) + h * HDIM + EMB;
    const size_t voff = koff + EMB;

    auto load_kv = [&](int j0, int buf) {
        uint32_t dstb = sb + (uint32_t)buf * (uint32_t)KVSTAGE;
#pragma unroll
        for (int it = 0; it < 8; it++) {
            int cch = tid + it * 256;
            int arr = cch >> 9;              // 0 Kh, 1 Kl, 2 Vh, 3 Vl
            int cc  = cch & 511;
            int r   = cc >> 3, ch = cc & 7;
            size_t goff = ((arr < 2) ? koff : voff)
                        + (size_t)(j0 + r) * (3 * EMB) + ch * 8;
            const char* src = (const char*)(((arr & 1) ? QKVl : QKVh) + goff);
            uint32_t dst = dstb + (uint32_t)arr * 8192u
                         + (uint32_t)(r * 128 + ((ch ^ (r & 7)) << 4));
            CP_ASYNC16(dst, src);
        }
    };

    // prologue: Q (hi+lo) into slot 2, then KV tiles 0,1 into slots 0,1
    {
        uint32_t sQh = sb + 2u * (uint32_t)KVSTAGE;
#pragma unroll
        for (int it = 0; it < 8; it++) {
            int cch = tid + it * 256;
            int arr = cch >> 10;             // 0 hi, 1 lo
            int cc  = cch & 1023;
            int r   = cc >> 3, ch = cc & 7;
            const char* src = (const char*)((arr ? QKVl : QKVh) + qoff
                                            + (size_t)r * (3 * EMB) + ch * 8);
            uint32_t dst = sQh + (uint32_t)arr * 16384u
                         + (uint32_t)(r * 128 + ((ch ^ (r & 7)) << 4));
            CP_ASYNC16(dst, src);
        }
    }
    CP_COMMIT();                 // group: Q
    load_kv(0, 0);
    CP_COMMIT();                 // group: kv0
    load_kv(64, 1);
    CP_COMMIT();                 // group: kv1

    // Q fragments -> registers (once)
    uint32_t qh[4][4], ql[4][4];
    CP_WAIT2();                  // Q resident (kv0, kv1 may be in flight)
    __syncthreads();
    {
        uint32_t sQh = sb + 2u * (uint32_t)KVSTAGE;
        int row = wid * 16 + (grp & 1) * 8 + l8;
#pragma unroll
        for (int kc = 0; kc < 4; kc++) {
            int ch = 2 * kc + (grp >> 1);
            uint32_t sw = (uint32_t)(row * 128 + ((ch ^ (row & 7)) << 4));
            ldsm4(qh[kc], sQh + sw);
            ldsm4(ql[kc], sQh + 16384u + sw);
        }
    }

    float m0 = -1e30f, m1 = -1e30f, l0 = 0.f, l1 = 0.f;
    float o[8][4];
#pragma unroll
    for (int d = 0; d < 8; d++)
#pragma unroll
        for (int q = 0; q < 4; q++) o[d][q] = 0.f;

    // softmax runs in exp2 domain; fold sm_scale * log2(e) into one multiply
    const float SCL = 0.125f * 1.44269504088896f;

    const int NKV = SEQ / 64;
    for (int jt = 0; jt < NKV; jt++) {
        int buf = jt % 3;
        if (jt + 1 < NKV) CP_WAIT1(); else CP_WAIT0();
        __syncthreads();
        // slot (jt+2)%3 == (jt-1)%3 was last read at tile jt-1 (or held Q,
        // fully consumed before the loop); barrier above protects it.
        if (jt + 2 < NKV) {
            load_kv((jt + 2) * 64, (jt + 2) % 3);
            CP_COMMIT();
        }

        uint32_t kb = sb + (uint32_t)buf * (uint32_t)KVSTAGE;

        // ---- S = Q @ K^T (split, 3 terms) ----
        float s[8][4];
#pragma unroll
        for (int nb = 0; nb < 8; nb++)
#pragma unroll
            for (int q = 0; q < 4; q++) s[nb][q] = 0.f;

#pragma unroll
        for (int kc = 0; kc < 4; kc++) {
#pragma unroll
            for (int ng = 0; ng < 4; ng++) {
                uint32_t kh[4], kl[4];
                int row = ng * 16 + (grp >> 1) * 8 + l8;
                int ch  = 2 * kc + (grp & 1);
                uint32_t sw = (uint32_t)(row * 128 + ((ch ^ (row & 7)) << 4));
                ldsm4(kh, kb + sw);
                ldsm4(kl, kb + 8192u + sw);
                mma16816(s[2 * ng],     qh[kc], kh[0], kh[1]);
                mma16816(s[2 * ng + 1], qh[kc], kh[2], kh[3]);
                mma16816(s[2 * ng],     qh[kc], kl[0], kl[1]);
                mma16816(s[2 * ng + 1], qh[kc], kl[2], kl[3]);
                mma16816(s[2 * ng],     ql[kc], kh[0], kh[1]);
                mma16816(s[2 * ng + 1], ql[kc], kh[2], kh[3]);
            }
        }

        // ---- online softmax (rows r = lane>>2 and r+8, quad-wide) ----
        float mx0 = -1e30f, mx1 = -1e30f;
#pragma unroll
        for (int nb = 0; nb < 8; nb++) {
#pragma unroll
            for (int q = 0; q < 4; q++) s[nb][q] *= SCL;
            mx0 = fmaxf(mx0, fmaxf(s[nb][0], s[nb][1]));
            mx1 = fmaxf(mx1, fmaxf(s[nb][2], s[nb][3]));
        }
        mx0 = fmaxf(mx0, __shfl_xor_sync(0xffffffffu, mx0, 1));
        mx0 = fmaxf(mx0, __shfl_xor_sync(0xffffffffu, mx0, 2));
        mx1 = fmaxf(mx1, __shfl_xor_sync(0xffffffffu, mx1, 1));
        mx1 = fmaxf(mx1, __shfl_xor_sync(0xffffffffu, mx1, 2));
        float mn0 = fmaxf(m0, mx0), mn1 = fmaxf(m1, mx1);
        float al0 = exp2f(m0 - mn0), al1 = exp2f(m1 - mn1);
        m0 = mn0; m1 = mn1;
        float rs0 = 0.f, rs1 = 0.f;
#pragma unroll
        for (int nb = 0; nb < 8; nb++) {
            s[nb][0] = exp2f(s[nb][0] - mn0);
            s[nb][1] = exp2f(s[nb][1] - mn0);
            s[nb][2] = exp2f(s[nb][2] - mn1);
            s[nb][3] = exp2f(s[nb][3] - mn1);
            rs0 += s[nb][0] + s[nb][1];
            rs1 += s[nb][2] + s[nb][3];
        }
        rs0 += __shfl_xor_sync(0xffffffffu, rs0, 1);
        rs0 += __shfl_xor_sync(0xffffffffu, rs0, 2);
        rs1 += __shfl_xor_sync(0xffffffffu, rs1, 1);
        rs1 += __shfl_xor_sync(0xffffffffu, rs1, 2);
        l0 = l0 * al0 + rs0;
        l1 = l1 * al1 + rs1;
#pragma unroll
        for (int d = 0; d < 8; d++) {
            o[d][0] *= al0; o[d][1] *= al0;
            o[d][2] *= al1; o[d][3] *= al1;
        }

        // ---- O += P @ V (split, 3 terms); P packed in-register ----
#pragma unroll
        for (int kc = 0; kc < 4; kc++) {
            uint32_t ph[4], pl[4];
            packsplit(s[2 * kc][0],     s[2 * kc][1],     ph[0], pl[0]);
            packsplit(s[2 * kc][2],     s[2 * kc][3],     ph[1], pl[1]);
            packsplit(s[2 * kc + 1][0], s[2 * kc + 1][1], ph[2], pl[2]);
            packsplit(s[2 * kc + 1][2], s[2 * kc + 1][3], ph[3], pl[3]);
#pragma unroll
            for (int dg = 0; dg < 4; dg++) {
                uint32_t vh[4], vl[4];
                int row = kc * 16 + (grp & 1) * 8 + l8;   // kv row
                int ch  = 2 * dg + (grp >> 1);            // d chunk
                uint32_t sw = (uint32_t)(row * 128 + ((ch ^ (row & 7)) << 4));
                ldsm4t(vh, kb + 16384u + sw);
                ldsm4t(vl, kb + 24576u + sw);
                mma16816(o[2 * dg],     ph, vh[0], vh[1]);
                mma16816(o[2 * dg + 1], ph, vh[2], vh[3]);
                mma16816(o[2 * dg],     ph, vl[0], vl[1]);
                mma16816(o[2 * dg + 1], ph, vl[2], vl[3]);
                mma16816(o[2 * dg],     pl, vh[0], vh[1]);
                mma16816(o[2 * dg + 1], pl, vh[2], vh[3]);
            }
        }
    }

    // epilogue: normalize, write bf16 hi/lo pairs to [M, E]
    float il0 = 1.f / l0, il1 = 1.f / l1;
    int rg0 = q0 + wid * 16 + (lane >> 2);
#pragma unroll
    for (int d = 0; d < 8; d++) {
        int col = h * HDIM + d * 8 + (lane & 3) * 2;
        size_t off0 = ((size_t)b * SEQ + rg0) * EMB + col;
        size_t off1 = ((size_t)b * SEQ + rg0 + 8) * EMB + col;
        uint32_t hi, lo;
        packsplit(o[d][0] * il0, o[d][1] * il0, hi, lo);
        *(uint32_t*)(Oh + off0) = hi;
        *(uint32_t*)(Ol + off0) = lo;
        packsplit(o[d][2] * il1, o[d][3] * il1, hi, lo);
        *(uint32_t*)(Oh + off1) = hi;
        *(uint32_t*)(Ol + off1) = lo;
    }
}

// ---------------------------------------------------------------------------
// Launch
// ---------------------------------------------------------------------------
extern "C" void kernel_launch(void* const* d_in, const int* in_sizes, int n_in,
                              void* d_out, int out_size)
{
    const float *x = nullptr, *Wqkv = nullptr, *bqkv = nullptr,
                *Wout = nullptr, *bout = nullptr;
    for (int i = 0; i < n_in; i++) {
        switch (in_sizes[i]) {
            case 4194304: x    = (const float*)d_in[i]; break;  // [2,2048,1024]
            case 3145728: Wqkv = (const float*)d_in[i]; break;  // [1024,3072]
            case 3072:    bqkv = (const float*)d_in[i]; break;
            case 1048576: Wout = (const float*)d_in[i]; break;  // [1024,1024]
            case 1024:    bout = (const float*)d_in[i]; break;
        }
    }
    float* out = (float*)d_out;

    __nv_bfloat16 *xh, *xl, *qkvh, *qkvl, *ah, *al, *wqh, *wql, *woh, *wol;
    cudaGetSymbolAddress((void**)&xh,   g_xh);
    cudaGetSymbolAddress((void**)&xl,   g_xl);
    cudaGetSymbolAddress((void**)&qkvh, g_qkvh);
    cudaGetSymbolAddress((void**)&qkvl, g_qkvl);
    cudaGetSymbolAddress((void**)&ah,   g_ah);
    cudaGetSymbolAddress((void**)&al,   g_al);
    cudaGetSymbolAddress((void**)&wqh,  g_wqh);
    cudaGetSymbolAddress((void**)&wql,  g_wql);
    cudaGetSymbolAddress((void**)&woh,  g_woh);
    cudaGetSymbolAddress((void**)&wol,  g_wol);

    cudaFuncSetAttribute(gemm_mma_kernel,
                         cudaFuncAttributeMaxDynamicSharedMemorySize, GEMM_SMEM);
    cudaFuncSetAttribute(flash_mma_kernel,
                         cudaFuncAttributeMaxDynamicSharedMemorySize, FLASH_SMEM);

    // 0a. split x -> bf16 hi/lo
    split_kernel<<<(MTOK * EMB / 4 + 255) / 256, 256>>>(x, xh, xl, MTOK * EMB / 4);
    // 0b. transpose + split weights
    {
        dim3 g1(3 * EMB / 32, EMB / 32);
        transpose_split_kernel<<<g1, dim3(32, 8)>>>(Wqkv, wqh, wql, EMB, 3 * EMB);
        dim3 g2(EMB / 32, EMB / 32);
        transpose_split_kernel<<<g2, dim3(32, 8)>>>(Wout, woh, wol, EMB, EMB);
    }
    // 1. QKV projection -> bf16 hi/lo qkv directly
    {
        dim3 grid(3 * EMB / 128, MTOK / 128);
        gemm_mma_kernel<<<grid, 256, GEMM_SMEM>>>(
            xh, xl, wqh, wql, bqkv, nullptr, qkvh, qkvl, MTOK, 3 * EMB, EMB);
    }
    // 2. Flash attention -> bf16 hi/lo attn output directly
    {
        dim3 grid(SEQ / 128, HEADS, BATCH);
        flash_mma_kernel<<<grid, 256, FLASH_SMEM>>>(qkvh, qkvl, ah, al);
    }
    // 3. Output projection -> fp32 final output
    {
        dim3 grid(EMB / 128, MTOK / 128);
        gemm_mma_kernel<<<grid, 256, GEMM_SMEM>>>(
            ah, al, woh, wol, bout, out, nullptr, nullptr, MTOK, EMB, EMB);
    }
}